// round 10
// baseline (speedup 1.0000x reference)
#include <cuda_runtime.h>
#include <cuda_bf16.h>
#include <float.h>
#include <stdint.h>

// Problem constants
#define BB   32
#define DD   256
#define HW   1024
#define NN   (BB*HW)       // 32768
#define KK   1024

#define ZQ_SIZE  (NN*DD)
#define IDX_OFF  ZQ_SIZE
#define LOSS_OFF (ZQ_SIZE + NN)

// GEMM tiling (mma.sync m16n8k16 bf16)
#define MT   128           // rows per CTA
#define NC   64            // codes per chunk
#define NCH  (KK/NC)       // 16 chunks
#define KSP  (DD/16)       // 16 k-steps of 16
#define CAP  8
#define WINDOW 4.0e-3f

// ---------------- helpers ----------------
__device__ __forceinline__ void mma_bf16(float* d, uint32_t a0, uint32_t a1,
                                         uint32_t a2, uint32_t a3,
                                         uint32_t b0, uint32_t b1) {
    asm volatile(
        "mma.sync.aligned.m16n8k16.row.col.f32.bf16.bf16.f32 "
        "{%0,%1,%2,%3}, {%4,%5,%6,%7}, {%8,%9}, {%0,%1,%2,%3};"
        : "+f"(d[0]), "+f"(d[1]), "+f"(d[2]), "+f"(d[3])
        : "r"(a0), "r"(a1), "r"(a2), "r"(a3), "r"(b0), "r"(b1));
}
__device__ __forceinline__ uint32_t pack_bf16(float lo, float hi) {
    __nv_bfloat162 h = __floats2bfloat162_rn(lo, hi);   // lo -> .x (low 16)
    return *(uint32_t*)&h;
}
// monotone float<->int map for atomicMin
__device__ __forceinline__ int   fmap(float f)  { int i = __float_as_int(f); return i < 0 ? (i ^ 0x7FFFFFFF) : i; }
__device__ __forceinline__ float funmap(int i)  { return __int_as_float(i < 0 ? (i ^ 0x7FFFFFFF) : i); }

// ---------------- scratch ----------------
__device__ float g_cbnorm[KK];
__device__ float g_znorm[NN];
__device__ float g_zt[(size_t)NN * DD];     // z transposed to [n][d]
__device__ int   g_idx[NN];
__device__ float g_partial[2048];
__device__ int   g_candk[(size_t)NN * CAP];
__device__ float g_candd[(size_t)NN * CAP];
__device__ float g_bestd[NN];
__device__ int   g_cnum[NN];

// ---------------- kernel 1a: codebook norms (exact sequential order, coalesced) ----
__global__ void cbnorm_kernel(const float* __restrict__ cb) {
    __shared__ float tile[128][65];
    const int t  = threadIdx.x;            // 128 threads, row per thread
    const int r0 = blockIdx.x * 128;
    float acc = 0.f;
    for (int p = 0; p < 4; p++) {
        __syncthreads();
        for (int i = t; i < 128 * 64; i += 128) {
            int row = i >> 6, dc = i & 63;
            tile[row][dc] = cb[(r0 + row) * DD + p * 64 + dc];
        }
        __syncthreads();
        #pragma unroll 8
        for (int d = 0; d < 64; d++) {
            float v = tile[t][d];
            acc = __fadd_rn(acc, __fmul_rn(v, v));
        }
    }
    g_cbnorm[r0 + t] = acc;
}

// ---------------- kernel 1b: z norms (proven exact order) ----------------
__global__ void znorm_kernel(const float* __restrict__ z) {
    int n = blockIdx.x * blockDim.x + threadIdx.x;
    if (n >= NN) return;
    int b  = n >> 10;
    int hw = n & 1023;
    const float* p = z + ((size_t)b << 18) + hw;
    float acc = 0.f;
    #pragma unroll 8
    for (int d = 0; d < DD; d++) {
        float v = p[(size_t)d << 10];
        acc = __fadd_rn(acc, __fmul_rn(v, v));
    }
    g_znorm[n] = acc;
}

// ---------------- kernel 1c: transpose z -> g_zt[n][d] ----------------
__global__ void transpose_kernel(const float* __restrict__ z) {
    __shared__ float tile[32][33];
    int b   = blockIdx.z;
    int hw0 = blockIdx.x * 32;
    int d0  = blockIdx.y * 32;
    int tx = threadIdx.x, ty = threadIdx.y;
    #pragma unroll
    for (int j = 0; j < 32; j += 8)
        tile[ty + j][tx] = z[((size_t)(b * DD + d0 + ty + j)) * HW + hw0 + tx];
    __syncthreads();
    #pragma unroll
    for (int j = 0; j < 32; j += 8)
        g_zt[((size_t)(b * HW + hw0 + ty + j)) * DD + d0 + tx] = tile[tx][ty + j];
}

// ---------------- kernel 2: bf16 MMA GEMM + fused min + windowed candidates ----
// 256 threads / 8 warps: 4 M-warps x 2 N-warps, warp tile 32x32.
// smem u32 layout: As[16][128][8] | Bs[16][64][8] | cn[1024] | s_min[128]
//                  | s_cnt[128] | s_ck[128][8] | s_cd[128][8]   = 109 KB -> 2 CTA/SM
// Word interleave per 16-k step: [w0,w4,w1,w5,w2,w6,w3,w7] (wi = k pair 2i,2i+1)
// so LDS.64 at pos 2*tg yields both fragment words per row/code.
__global__ void __launch_bounds__(256, 2)
mma_cand_kernel(const float* __restrict__ cb) {
    extern __shared__ uint32_t smu[];
    uint32_t* As   = smu;                         // 16384 u32
    uint32_t* Bs   = smu + 16 * 128 * 8;          // 8192 u32
    float*    cn   = (float*)(Bs + 16 * 64 * 8);  // 1024
    int*      smin = (int*)(cn + KK);             // 128
    int*      scnt = smin + 128;                  // 128
    int*      sck  = scnt + 128;                  // 128*8
    float*    scd  = (float*)(sck + 128 * CAP);   // 128*8

    const int t    = threadIdx.x;
    const int lane = t & 31;
    const int wid  = t >> 5;
    const int wm   = wid & 3;            // 4 warps over M (32 rows)
    const int wn   = wid >> 2;           // 2 warps over N (32 cols)
    const int g    = lane >> 2;
    const int tg   = lane & 3;
    const int n0   = blockIdx.x * MT;

    for (int i = t; i < KK; i += 256) cn[i] = g_cbnorm[i];
    if (t < MT) { smin[t] = fmap(FLT_MAX); scnt[t] = 0; }

    // stage A: 128 rows x 256 k -> bf16, interleaved words
    for (int i4 = t; i4 < MT * DD / 4; i4 += 256) {
        int row = i4 >> 6, k4 = i4 & 63;
        float4 v = *(const float4*)(g_zt + (size_t)(n0 + row) * DD + k4 * 4);
        int ks = k4 >> 2;
        int q  = k4 & 3;
        int pos0 = (q < 2) ? q * 4 : (q - 2) * 4 + 1;   // q:0->0, 1->4, 2->1, 3->5
        uint32_t* dst = As + ((ks * MT + row) << 3);
        dst[pos0]     = pack_bf16(v.x, v.y);
        dst[pos0 + 2] = pack_bf16(v.z, v.w);
    }

    // per-lane zn for its 4 rows (mf 0/1 x row g/g+8)
    float znr[2][2];
    #pragma unroll
    for (int mf = 0; mf < 2; mf++) {
        znr[mf][0] = g_znorm[n0 + wm * 32 + mf * 16 + g];
        znr[mf][1] = g_znorm[n0 + wm * 32 + mf * 16 + g + 8];
    }

    for (int c = 0; c < NCH; c++) {
        const int c0 = c * NC;
        __syncthreads();   // prev admission done; Bs free (also A/init ready, iter 0)

        // stage B: 64 codes x 256 k -> bf16, interleaved words
        for (int i4 = t; i4 < NC * DD / 4; i4 += 256) {
            int row = i4 >> 6, k4 = i4 & 63;
            float4 v = *(const float4*)(cb + (size_t)(c0 + row) * DD + k4 * 4);
            int ks = k4 >> 2;
            int q  = k4 & 3;
            int pos0 = (q < 2) ? q * 4 : (q - 2) * 4 + 1;
            uint32_t* dst = Bs + ((ks * NC + row) << 3);
            dst[pos0]     = pack_bf16(v.x, v.y);
            dst[pos0 + 2] = pack_bf16(v.z, v.w);
        }
        __syncthreads();

        float acc[2][4][4];
        #pragma unroll
        for (int mf = 0; mf < 2; mf++)
            #pragma unroll
            for (int nf = 0; nf < 4; nf++)
                #pragma unroll
                for (int e = 0; e < 4; e++) acc[mf][nf][e] = 0.f;

        #pragma unroll 4
        for (int ks = 0; ks < KSP; ks++) {
            uint2 alo[2], ahi[2];
            #pragma unroll
            for (int mf = 0; mf < 2; mf++) {
                int r = wm * 32 + mf * 16 + g;
                alo[mf] = *(const uint2*)(As + ((ks * MT + r) << 3) + 2 * tg);
                ahi[mf] = *(const uint2*)(As + ((ks * MT + r + 8) << 3) + 2 * tg);
            }
            uint2 bf[4];
            #pragma unroll
            for (int nf = 0; nf < 4; nf++) {
                int cc = wn * 32 + nf * 8 + g;
                bf[nf] = *(const uint2*)(Bs + ((ks * NC + cc) << 3) + 2 * tg);
            }
            #pragma unroll
            for (int mf = 0; mf < 2; mf++)
                #pragma unroll
                for (int nf = 0; nf < 4; nf++)
                    mma_bf16(acc[mf][nf], alo[mf].x, ahi[mf].x, alo[mf].y, ahi[mf].y,
                             bf[nf].x, bf[nf].y);
        }

        // phase 1: per-row running min -> smem atomicMin
        float rmin[2][2];
        #pragma unroll
        for (int mf = 0; mf < 2; mf++) { rmin[mf][0] = FLT_MAX; rmin[mf][1] = FLT_MAX; }
        #pragma unroll
        for (int mf = 0; mf < 2; mf++)
            #pragma unroll
            for (int nf = 0; nf < 4; nf++) {
                int col0 = wn * 32 + nf * 8 + 2 * tg;
                float c0v = cn[c0 + col0], c1v = cn[c0 + col0 + 1];
                rmin[mf][0] = fminf(rmin[mf][0],
                    fminf((znr[mf][0] + c0v) - 2.f * acc[mf][nf][0],
                          (znr[mf][0] + c1v) - 2.f * acc[mf][nf][1]));
                rmin[mf][1] = fminf(rmin[mf][1],
                    fminf((znr[mf][1] + c0v) - 2.f * acc[mf][nf][2],
                          (znr[mf][1] + c1v) - 2.f * acc[mf][nf][3]));
            }
        #pragma unroll
        for (int mf = 0; mf < 2; mf++)
            #pragma unroll
            for (int rr = 0; rr < 2; rr++) {
                float m = rmin[mf][rr];
                m = fminf(m, __shfl_xor_sync(0xFFFFFFFFu, m, 1));
                m = fminf(m, __shfl_xor_sync(0xFFFFFFFFu, m, 2));
                rmin[mf][rr] = m;
            }
        if (tg == 0) {
            #pragma unroll
            for (int mf = 0; mf < 2; mf++) {
                atomicMin(&smin[wm * 32 + mf * 16 + g],     fmap(rmin[mf][0]));
                atomicMin(&smin[wm * 32 + mf * 16 + g + 8], fmap(rmin[mf][1]));
            }
        }
        __syncthreads();

        // phase 2: windowed admission vs updated running min
        #pragma unroll
        for (int mf = 0; mf < 2; mf++) {
            int r0 = wm * 32 + mf * 16 + g;
            float th0 = funmap(smin[r0])     + WINDOW;
            float th1 = funmap(smin[r0 + 8]) + WINDOW;
            #pragma unroll
            for (int nf = 0; nf < 4; nf++) {
                int col0 = wn * 32 + nf * 8 + 2 * tg;
                float c0v = cn[c0 + col0], c1v = cn[c0 + col0 + 1];
                float d00 = (znr[mf][0] + c0v) - 2.f * acc[mf][nf][0];
                float d01 = (znr[mf][0] + c1v) - 2.f * acc[mf][nf][1];
                float d10 = (znr[mf][1] + c0v) - 2.f * acc[mf][nf][2];
                float d11 = (znr[mf][1] + c1v) - 2.f * acc[mf][nf][3];
                if (d00 <= th0) { int p = atomicAdd(&scnt[r0], 1);     if (p < CAP) { sck[r0 * CAP + p] = c0 + col0;           scd[r0 * CAP + p] = d00; } }
                if (d01 <= th0) { int p = atomicAdd(&scnt[r0], 1);     if (p < CAP) { sck[r0 * CAP + p] = c0 + col0 + 1;       scd[r0 * CAP + p] = d01; } }
                if (d10 <= th1) { int p = atomicAdd(&scnt[r0 + 8], 1); if (p < CAP) { sck[(r0 + 8) * CAP + p] = c0 + col0;     scd[(r0 + 8) * CAP + p] = d10; } }
                if (d11 <= th1) { int p = atomicAdd(&scnt[r0 + 8], 1); if (p < CAP) { sck[(r0 + 8) * CAP + p] = c0 + col0 + 1; scd[(r0 + 8) * CAP + p] = d11; } }
            }
        }
    }
    __syncthreads();

    // flush per-row results
    if (t < MT) {
        int cnt = scnt[t];
        g_bestd[n0 + t] = funmap(smin[t]);
        g_cnum[n0 + t]  = (cnt > CAP) ? 255 : cnt;
        int m = (cnt > CAP) ? CAP : cnt;
        for (int q = 0; q < m; q++) {
            g_candk[(size_t)(n0 + t) * CAP + q] = sck[t * CAP + q];
            g_candd[(size_t)(n0 + t) * CAP + q] = scd[t * CAP + q];
        }
    }
}

// ---------------- kernel 2b: finalize — filter candidates, exact rescore ----
__global__ void finalize_kernel(const float* __restrict__ cb) {
    const int t = threadIdx.x, w = t >> 5, l = t & 31;
    const int n = blockIdx.x * 8 + w;

    int cnum = g_cnum[n];
    const float bstd = g_bestd[n];

    if (cnum != 255) {
        int m2 = 0, lastk = 0;
        for (int c = 0; c < cnum; c++)
            if (g_candd[(size_t)n * CAP + c] <= bstd + WINDOW) {
                m2++; lastk = g_candk[(size_t)n * CAP + c];
            }
        if (m2 == 1) {                  // sound: true argmin is always admitted
            if (l == 0) g_idx[n] = lastk;
            return;
        }
    }

    const float zn  = g_znorm[n];
    const float* zr = g_zt + (size_t)n * DD;
    float zv[8];
    #pragma unroll
    for (int j = 0; j < 8; j++) zv[j] = zr[l + 32 * j];

    float bd = FLT_MAX;
    int   bk = 0x7FFFFFFF;
    const int cmax = (cnum == 255) ? KK : cnum;
    for (int c = 0; c < cmax; c++) {
        int k;
        if (cnum == 255) k = c;
        else {
            k = g_candk[(size_t)n * CAP + c];
            if (g_candd[(size_t)n * CAP + c] > bstd + WINDOW) continue;
        }
        const float* er = cb + (size_t)k * DD;
        float s = 0.f;
        #pragma unroll
        for (int j = 0; j < 8; j++) s = fmaf(zv[j], er[l + 32 * j], s);
        #pragma unroll
        for (int off = 16; off; off >>= 1) s += __shfl_xor_sync(0xFFFFFFFFu, s, off);
        // reference rounding: RN( RN(zn + cn) - 2*dot )
        float dist = __fadd_rn(__fadd_rn(zn, g_cbnorm[k]), -2.0f * s);
        if (dist < bd || (dist == bd && k < bk)) { bd = dist; bk = k; }
    }
    if (l == 0) g_idx[n] = bk;
}

// ---------------- kernel 3: gather + zq_st + indices + loss partials ----------
#define GN 128
#define GD 32
__global__ void gather_kernel(const float* __restrict__ z,
                              const float* __restrict__ cb,
                              float* __restrict__ out,
                              int write_extra) {
    __shared__ int   sidx[GN];
    __shared__ float tile[GD][GN + 1];
    __shared__ float red[8];

    const int t   = threadIdx.x;
    const int n0  = blockIdx.x * GN;
    const int d0  = blockIdx.y * GD;
    const int b   = n0 >> 10;
    const int hw0 = n0 & 1023;

    if (t < GN) sidx[t] = g_idx[n0 + t];
    __syncthreads();

    const int w = t >> 5, l = t & 31;
    for (int nn = w; nn < GN; nn += 8)
        tile[l][nn] = cb[sidx[nn] * DD + d0 + l];
    __syncthreads();

    float lsum = 0.f;
    #pragma unroll
    for (int r = 0; r < (GD * GN) / 256; r++) {
        int i  = r * 256 + t;
        int dd = i >> 7;
        int n  = i & 127;
        int d  = d0 + dd;
        float q  = tile[dd][n];
        int   zi = ((b << 8) + d) * HW + hw0 + n;
        float zv = z[zi];
        float df = __fsub_rn(q, zv);
        out[zi] = __fadd_rn(zv, df);       // zq_st = zp + RN(zq - zp), bitwise
        lsum = fmaf(df, df, lsum);
    }

    #pragma unroll
    for (int off = 16; off; off >>= 1)
        lsum += __shfl_xor_sync(0xFFFFFFFFu, lsum, off);
    if (l == 0) red[w] = lsum;
    __syncthreads();
    if (t == 0) {
        float s = 0.f;
        #pragma unroll
        for (int i = 0; i < 8; i++) s += red[i];
        g_partial[blockIdx.y * gridDim.x + blockIdx.x] = s;
    }
    if (write_extra && blockIdx.y == 0 && t < GN)
        out[IDX_OFF + n0 + t] = (float)sidx[t];
}

// ---------------- kernel 4: finalize loss ----------------
__global__ void loss_kernel(float* __restrict__ out) {
    __shared__ float red[8];
    int t = threadIdx.x;
    float s = 0.f;
    #pragma unroll
    for (int i = 0; i < 8; i++)
        s += g_partial[t * 8 + i];
    #pragma unroll
    for (int off = 16; off; off >>= 1)
        s += __shfl_xor_sync(0xFFFFFFFFu, s, off);
    if ((t & 31) == 0) red[t >> 5] = s;
    __syncthreads();
    if (t == 0) {
        double tot = 0.0;
        #pragma unroll
        for (int i = 0; i < 8; i++) tot += (double)red[i];
        out[LOSS_OFF] = (float)(2.0 * tot / (double)ZQ_SIZE);
    }
}

// ---------------- launch ----------------
extern "C" void kernel_launch(void* const* d_in, const int* in_sizes, int n_in,
                              void* d_out, int out_size) {
    const float* z  = (const float*)d_in[0];
    const float* cb = (const float*)d_in[1];
    float* out = (float*)d_out;

    int write_extra = (out_size >= LOSS_OFF + 1) ? 1 : 0;

    cbnorm_kernel<<<KK / 128, 128>>>(cb);
    znorm_kernel<<<NN / 256, 256>>>(z);
    transpose_kernel<<<dim3(HW / 32, DD / 32, BB), dim3(32, 8)>>>(z);

    // smem: As 64K + Bs 32K + cn 4K + smin/scnt 1K + cand 8K = 109.0 KB
    size_t smem = (16 * 128 * 8 + 16 * 64 * 8 + KK + 128 + 128 + 128 * CAP) * 4
                  + 128 * CAP * 4;
    cudaFuncSetAttribute(mma_cand_kernel,
                         cudaFuncAttributeMaxDynamicSharedMemorySize, (int)smem);
    mma_cand_kernel<<<NN / MT, 256, smem>>>(cb);

    finalize_kernel<<<NN / 8, 256>>>(cb);

    gather_kernel<<<dim3(NN / GN, DD / GD), 256>>>(z, cb, out, write_extra);

    if (write_extra)
        loss_kernel<<<1, 256>>>(out);
}

// round 11
// speedup vs baseline: 2.6823x; 2.6823x over previous
#include <cuda_runtime.h>
#include <cuda_bf16.h>
#include <float.h>
#include <stdint.h>

// Problem constants
#define BB   32
#define DD   256
#define HW   1024
#define NN   (BB*HW)       // 32768
#define KK   1024

#define ZQ_SIZE  (NN*DD)
#define IDX_OFF  ZQ_SIZE
#define LOSS_OFF (ZQ_SIZE + NN)

// GEMM tiling (mma.sync m16n8k16 bf16)
#define MT   128           // rows per CTA
#define NC   64            // codes per chunk
#define NCH  (KK/NC)       // 16 chunks
#define KSP  (DD/16)       // 16 k-steps of 16
#define CAP  16
#define WINDOW 4.0e-3f

// ---------------- helpers ----------------
__device__ __forceinline__ void mma_bf16(float* d, uint32_t a0, uint32_t a1,
                                         uint32_t a2, uint32_t a3,
                                         uint32_t b0, uint32_t b1) {
    asm volatile(
        "mma.sync.aligned.m16n8k16.row.col.f32.bf16.bf16.f32 "
        "{%0,%1,%2,%3}, {%4,%5,%6,%7}, {%8,%9}, {%0,%1,%2,%3};"
        : "+f"(d[0]), "+f"(d[1]), "+f"(d[2]), "+f"(d[3])
        : "r"(a0), "r"(a1), "r"(a2), "r"(a3), "r"(b0), "r"(b1));
}
__device__ __forceinline__ uint32_t pack_bf16(float lo, float hi) {
    __nv_bfloat162 h = __floats2bfloat162_rn(lo, hi);   // lo -> .x (low 16)
    return *(uint32_t*)&h;
}
// monotone float<->int map for atomicMin
__device__ __forceinline__ int   fmap(float f)  { int i = __float_as_int(f); return i < 0 ? (i ^ 0x7FFFFFFF) : i; }
__device__ __forceinline__ float funmap(int i)  { return __int_as_float(i < 0 ? (i ^ 0x7FFFFFFF) : i); }

// ---------------- scratch ----------------
__device__ float g_cbnorm[KK];
__device__ float g_znorm[NN];
__device__ float g_zt[(size_t)NN * DD];     // z transposed to [n][d]
__device__ int   g_idx[NN];
__device__ float g_partial[2048];
__device__ int   g_candk[(size_t)NN * CAP];
__device__ int   g_cnum[NN];

// ---------------- kernel 1a: codebook norms (exact sequential order, coalesced) ----
__global__ void cbnorm_kernel(const float* __restrict__ cb) {
    __shared__ float tile[128][65];
    const int t  = threadIdx.x;            // 128 threads, row per thread
    const int r0 = blockIdx.x * 128;
    float acc = 0.f;
    for (int p = 0; p < 4; p++) {
        __syncthreads();
        for (int i = t; i < 128 * 64; i += 128) {
            int row = i >> 6, dc = i & 63;
            tile[row][dc] = cb[(r0 + row) * DD + p * 64 + dc];
        }
        __syncthreads();
        #pragma unroll 8
        for (int d = 0; d < 64; d++) {
            float v = tile[t][d];
            acc = __fadd_rn(acc, __fmul_rn(v, v));
        }
    }
    g_cbnorm[r0 + t] = acc;
}

// ---------------- kernel 1b: z norms (proven exact order) ----------------
__global__ void znorm_kernel(const float* __restrict__ z) {
    int n = blockIdx.x * blockDim.x + threadIdx.x;
    if (n >= NN) return;
    int b  = n >> 10;
    int hw = n & 1023;
    const float* p = z + ((size_t)b << 18) + hw;
    float acc = 0.f;
    #pragma unroll 8
    for (int d = 0; d < DD; d++) {
        float v = p[(size_t)d << 10];
        acc = __fadd_rn(acc, __fmul_rn(v, v));
    }
    g_znorm[n] = acc;
}

// ---------------- kernel 1c: transpose z -> g_zt[n][d] ----------------
__global__ void transpose_kernel(const float* __restrict__ z) {
    __shared__ float tile[32][33];
    int b   = blockIdx.z;
    int hw0 = blockIdx.x * 32;
    int d0  = blockIdx.y * 32;
    int tx = threadIdx.x, ty = threadIdx.y;
    #pragma unroll
    for (int j = 0; j < 32; j += 8)
        tile[ty + j][tx] = z[((size_t)(b * DD + d0 + ty + j)) * HW + hw0 + tx];
    __syncthreads();
    #pragma unroll
    for (int j = 0; j < 32; j += 8)
        g_zt[((size_t)(b * HW + hw0 + ty + j)) * DD + d0 + tx] = tile[tx][ty + j];
}

// ---------------- kernel 2: bf16 MMA GEMM + fused min + windowed candidates ----
// 256 threads / 8 warps: 4 M-warps x 2 N-warps, warp tile 32x32.
// smem u32: As[16][128][8] | Bs[16][64][8] | cn[1024] | smin[128] | scnt[128]
//           | sck[128][16]   = 109 KB -> 2 CTA/SM
// Word interleave per 16-k step: [w0,w4,w1,w5,w2,w6,w3,w7] (wi = k pair 2i,2i+1)
// so LDS.64 at pos 2*tg yields both fragment words per row/code.
__global__ void __launch_bounds__(256, 2)
mma_cand_kernel(const float* __restrict__ cb) {
    extern __shared__ uint32_t smu[];
    uint32_t* As   = smu;                         // 16384 u32
    uint32_t* Bs   = smu + 16 * 128 * 8;          // 8192 u32
    float*    cn   = (float*)(Bs + 16 * 64 * 8);  // 1024
    int*      smin = (int*)(cn + KK);             // 128
    int*      scnt = smin + 128;                  // 128
    int*      sck  = scnt + 128;                  // 128*16

    const int t    = threadIdx.x;
    const int lane = t & 31;
    const int wid  = t >> 5;
    const int wm   = wid & 3;            // 4 warps over M (32 rows)
    const int wn   = wid >> 2;           // 2 warps over N (32 cols)
    const int g    = lane >> 2;
    const int tg   = lane & 3;
    const int n0   = blockIdx.x * MT;

    for (int i = t; i < KK; i += 256) cn[i] = g_cbnorm[i];
    if (t < MT) { smin[t] = fmap(FLT_MAX); scnt[t] = 0; }

    // stage A: 128 rows x 256 k -> bf16, interleaved words
    for (int i4 = t; i4 < MT * DD / 4; i4 += 256) {
        int row = i4 >> 6, k4 = i4 & 63;
        float4 v = *(const float4*)(g_zt + (size_t)(n0 + row) * DD + k4 * 4);
        int ks = k4 >> 2;
        int q  = k4 & 3;
        int pos0 = (q < 2) ? q * 4 : (q - 2) * 4 + 1;   // q:0->0, 1->4, 2->1, 3->5
        uint32_t* dst = As + ((ks * MT + row) << 3);
        dst[pos0]     = pack_bf16(v.x, v.y);
        dst[pos0 + 2] = pack_bf16(v.z, v.w);
    }

    // per-lane zn for its 4 rows (mf 0/1 x row g/g+8)
    float znr[2][2];
    #pragma unroll
    for (int mf = 0; mf < 2; mf++) {
        znr[mf][0] = g_znorm[n0 + wm * 32 + mf * 16 + g];
        znr[mf][1] = g_znorm[n0 + wm * 32 + mf * 16 + g + 8];
    }

    for (int c = 0; c < NCH; c++) {
        const int c0 = c * NC;
        __syncthreads();   // prev admission done; Bs free (also A/init ready, iter 0)

        // stage B: 64 codes x 256 k -> bf16, interleaved words
        for (int i4 = t; i4 < NC * DD / 4; i4 += 256) {
            int row = i4 >> 6, k4 = i4 & 63;
            float4 v = *(const float4*)(cb + (size_t)(c0 + row) * DD + k4 * 4);
            int ks = k4 >> 2;
            int q  = k4 & 3;
            int pos0 = (q < 2) ? q * 4 : (q - 2) * 4 + 1;
            uint32_t* dst = Bs + ((ks * NC + row) << 3);
            dst[pos0]     = pack_bf16(v.x, v.y);
            dst[pos0 + 2] = pack_bf16(v.z, v.w);
        }
        __syncthreads();

        float acc[2][4][4];
        #pragma unroll
        for (int mf = 0; mf < 2; mf++)
            #pragma unroll
            for (int nf = 0; nf < 4; nf++)
                #pragma unroll
                for (int e = 0; e < 4; e++) acc[mf][nf][e] = 0.f;

        #pragma unroll 4
        for (int ks = 0; ks < KSP; ks++) {
            uint2 alo[2], ahi[2];
            #pragma unroll
            for (int mf = 0; mf < 2; mf++) {
                int r = wm * 32 + mf * 16 + g;
                alo[mf] = *(const uint2*)(As + ((ks * MT + r) << 3) + 2 * tg);
                ahi[mf] = *(const uint2*)(As + ((ks * MT + r + 8) << 3) + 2 * tg);
            }
            uint2 bf[4];
            #pragma unroll
            for (int nf = 0; nf < 4; nf++) {
                int cc = wn * 32 + nf * 8 + g;
                bf[nf] = *(const uint2*)(Bs + ((ks * NC + cc) << 3) + 2 * tg);
            }
            #pragma unroll
            for (int mf = 0; mf < 2; mf++)
                #pragma unroll
                for (int nf = 0; nf < 4; nf++)
                    mma_bf16(acc[mf][nf], alo[mf].x, ahi[mf].x, alo[mf].y, ahi[mf].y,
                             bf[nf].x, bf[nf].y);
        }

        // phase 1: per-row running min -> smem atomicMin
        float rmin[2][2];
        #pragma unroll
        for (int mf = 0; mf < 2; mf++) { rmin[mf][0] = FLT_MAX; rmin[mf][1] = FLT_MAX; }
        #pragma unroll
        for (int mf = 0; mf < 2; mf++)
            #pragma unroll
            for (int nf = 0; nf < 4; nf++) {
                int col0 = wn * 32 + nf * 8 + 2 * tg;
                float c0v = cn[c0 + col0], c1v = cn[c0 + col0 + 1];
                rmin[mf][0] = fminf(rmin[mf][0],
                    fminf((znr[mf][0] + c0v) - 2.f * acc[mf][nf][0],
                          (znr[mf][0] + c1v) - 2.f * acc[mf][nf][1]));
                rmin[mf][1] = fminf(rmin[mf][1],
                    fminf((znr[mf][1] + c0v) - 2.f * acc[mf][nf][2],
                          (znr[mf][1] + c1v) - 2.f * acc[mf][nf][3]));
            }
        #pragma unroll
        for (int mf = 0; mf < 2; mf++)
            #pragma unroll
            for (int rr = 0; rr < 2; rr++) {
                float m = rmin[mf][rr];
                m = fminf(m, __shfl_xor_sync(0xFFFFFFFFu, m, 1));
                m = fminf(m, __shfl_xor_sync(0xFFFFFFFFu, m, 2));
                rmin[mf][rr] = m;
            }
        if (tg == 0) {
            #pragma unroll
            for (int mf = 0; mf < 2; mf++) {
                atomicMin(&smin[wm * 32 + mf * 16 + g],     fmap(rmin[mf][0]));
                atomicMin(&smin[wm * 32 + mf * 16 + g + 8], fmap(rmin[mf][1]));
            }
        }
        __syncthreads();

        // phase 2: windowed admission (key only) vs updated running min
        #pragma unroll
        for (int mf = 0; mf < 2; mf++) {
            int r0 = wm * 32 + mf * 16 + g;
            float th0 = funmap(smin[r0])     + WINDOW;
            float th1 = funmap(smin[r0 + 8]) + WINDOW;
            #pragma unroll
            for (int nf = 0; nf < 4; nf++) {
                int col0 = wn * 32 + nf * 8 + 2 * tg;
                float c0v = cn[c0 + col0], c1v = cn[c0 + col0 + 1];
                float d00 = (znr[mf][0] + c0v) - 2.f * acc[mf][nf][0];
                float d01 = (znr[mf][0] + c1v) - 2.f * acc[mf][nf][1];
                float d10 = (znr[mf][1] + c0v) - 2.f * acc[mf][nf][2];
                float d11 = (znr[mf][1] + c1v) - 2.f * acc[mf][nf][3];
                if (d00 <= th0) { int p = atomicAdd(&scnt[r0], 1);     if (p < CAP) sck[r0 * CAP + p] = c0 + col0; }
                if (d01 <= th0) { int p = atomicAdd(&scnt[r0], 1);     if (p < CAP) sck[r0 * CAP + p] = c0 + col0 + 1; }
                if (d10 <= th1) { int p = atomicAdd(&scnt[r0 + 8], 1); if (p < CAP) sck[(r0 + 8) * CAP + p] = c0 + col0; }
                if (d11 <= th1) { int p = atomicAdd(&scnt[r0 + 8], 1); if (p < CAP) sck[(r0 + 8) * CAP + p] = c0 + col0 + 1; }
            }
        }
    }
    __syncthreads();

    // flush per-row results
    if (t < MT) {
        int cnt = scnt[t];
        g_cnum[n0 + t] = (cnt > CAP) ? 255 : cnt;
        int m = (cnt > CAP) ? CAP : cnt;
        for (int q = 0; q < m; q++)
            g_candk[(size_t)(n0 + t) * CAP + q] = sck[t * CAP + q];
    }
}

// ---------------- kernel 2b: finalize — exact rescore of all candidates ----
// Warp per row. Mean ~6 candidates; codebook is L2-resident. Bit-exact
// reference rounding + (dist, k) lowest-index tiebreak.
__global__ void finalize_kernel(const float* __restrict__ cb) {
    const int t = threadIdx.x, w = t >> 5, l = t & 31;
    const int n = blockIdx.x * 8 + w;

    const int cnum = g_cnum[n];
    const float zn = g_znorm[n];
    const float* zr = g_zt + (size_t)n * DD;
    float zv[8];
    #pragma unroll
    for (int j = 0; j < 8; j++) zv[j] = zr[l + 32 * j];

    float bd = FLT_MAX;
    int   bk = 0x7FFFFFFF;
    const int cmax = (cnum == 255) ? KK : cnum;   // overflow (never expected) -> full scan
    for (int c = 0; c < cmax; c++) {
        int k = (cnum == 255) ? c : g_candk[(size_t)n * CAP + c];
        const float* er = cb + (size_t)k * DD;
        float s = 0.f;
        #pragma unroll
        for (int j = 0; j < 8; j++) s = fmaf(zv[j], er[l + 32 * j], s);
        #pragma unroll
        for (int off = 16; off; off >>= 1) s += __shfl_xor_sync(0xFFFFFFFFu, s, off);
        // reference rounding: RN( RN(zn + cn) - 2*dot )
        float dist = __fadd_rn(__fadd_rn(zn, g_cbnorm[k]), -2.0f * s);
        if (dist < bd || (dist == bd && k < bk)) { bd = dist; bk = k; }
    }
    if (l == 0) g_idx[n] = bk;
}

// ---------------- kernel 3: gather + zq_st + indices + loss partials ----------
#define GN 128
#define GD 32
__global__ void gather_kernel(const float* __restrict__ z,
                              const float* __restrict__ cb,
                              float* __restrict__ out,
                              int write_extra) {
    __shared__ int   sidx[GN];
    __shared__ float tile[GD][GN + 1];
    __shared__ float red[8];

    const int t   = threadIdx.x;
    const int n0  = blockIdx.x * GN;
    const int d0  = blockIdx.y * GD;
    const int b   = n0 >> 10;
    const int hw0 = n0 & 1023;

    if (t < GN) sidx[t] = g_idx[n0 + t];
    __syncthreads();

    const int w = t >> 5, l = t & 31;
    for (int nn = w; nn < GN; nn += 8)
        tile[l][nn] = cb[sidx[nn] * DD + d0 + l];
    __syncthreads();

    float lsum = 0.f;
    #pragma unroll
    for (int r = 0; r < (GD * GN) / 256; r++) {
        int i  = r * 256 + t;
        int dd = i >> 7;
        int n  = i & 127;
        int d  = d0 + dd;
        float q  = tile[dd][n];
        int   zi = ((b << 8) + d) * HW + hw0 + n;
        float zv = z[zi];
        float df = __fsub_rn(q, zv);
        out[zi] = __fadd_rn(zv, df);       // zq_st = zp + RN(zq - zp), bitwise
        lsum = fmaf(df, df, lsum);
    }

    #pragma unroll
    for (int off = 16; off; off >>= 1)
        lsum += __shfl_xor_sync(0xFFFFFFFFu, lsum, off);
    if (l == 0) red[w] = lsum;
    __syncthreads();
    if (t == 0) {
        float s = 0.f;
        #pragma unroll
        for (int i = 0; i < 8; i++) s += red[i];
        g_partial[blockIdx.y * gridDim.x + blockIdx.x] = s;
    }
    if (write_extra && blockIdx.y == 0 && t < GN)
        out[IDX_OFF + n0 + t] = (float)sidx[t];
}

// ---------------- kernel 4: finalize loss ----------------
__global__ void loss_kernel(float* __restrict__ out) {
    __shared__ float red[8];
    int t = threadIdx.x;
    float s = 0.f;
    #pragma unroll
    for (int i = 0; i < 8; i++)
        s += g_partial[t * 8 + i];
    #pragma unroll
    for (int off = 16; off; off >>= 1)
        s += __shfl_xor_sync(0xFFFFFFFFu, s, off);
    if ((t & 31) == 0) red[t >> 5] = s;
    __syncthreads();
    if (t == 0) {
        double tot = 0.0;
        #pragma unroll
        for (int i = 0; i < 8; i++) tot += (double)red[i];
        out[LOSS_OFF] = (float)(2.0 * tot / (double)ZQ_SIZE);
    }
}

// ---------------- launch ----------------
extern "C" void kernel_launch(void* const* d_in, const int* in_sizes, int n_in,
                              void* d_out, int out_size) {
    const float* z  = (const float*)d_in[0];
    const float* cb = (const float*)d_in[1];
    float* out = (float*)d_out;

    int write_extra = (out_size >= LOSS_OFF + 1) ? 1 : 0;

    cbnorm_kernel<<<KK / 128, 128>>>(cb);
    znorm_kernel<<<NN / 256, 256>>>(z);
    transpose_kernel<<<dim3(HW / 32, DD / 32, BB), dim3(32, 8)>>>(z);

    // smem: As 64K + Bs 32K + cn 4K + smin/scnt 1K + sck 8K = 109 KB
    size_t smem = (16 * 128 * 8 + 16 * 64 * 8 + KK + 128 + 128 + 128 * CAP) * 4;
    cudaFuncSetAttribute(mma_cand_kernel,
                         cudaFuncAttributeMaxDynamicSharedMemorySize, (int)smem);
    mma_cand_kernel<<<NN / MT, 256, smem>>>(cb);

    finalize_kernel<<<NN / 8, 256>>>(cb);

    gather_kernel<<<dim3(NN / GN, DD / GD), 256>>>(z, cb, out, write_extra);

    if (write_extra)
        loss_kernel<<<1, 256>>>(out);
}

// round 12
// speedup vs baseline: 6.2731x; 2.3387x over previous
#include <cuda_runtime.h>
#include <cuda_bf16.h>
#include <float.h>
#include <stdint.h>

// Problem constants
#define BB   32
#define DD   256
#define HW   1024
#define NN   (BB*HW)       // 32768
#define KK   1024

#define ZQ_SIZE  (NN*DD)
#define IDX_OFF  ZQ_SIZE
#define LOSS_OFF (ZQ_SIZE + NN)

// GEMM tiling (mma.sync m16n8k16 bf16)
#define MT   128           // rows per CTA
#define NC   64            // codes per chunk
#define NCH  (KK/NC)       // 16 chunks
#define KSP  (DD/16)       // 16 k-steps of 16
#define CAP  16            // smem candidate slots per row
#define EXT  48            // global spill slots per row
#define WINDOW 2.0e-3f

// ---------------- helpers ----------------
__device__ __forceinline__ void mma_bf16(float* d, uint32_t a0, uint32_t a1,
                                         uint32_t a2, uint32_t a3,
                                         uint32_t b0, uint32_t b1) {
    asm volatile(
        "mma.sync.aligned.m16n8k16.row.col.f32.bf16.bf16.f32 "
        "{%0,%1,%2,%3}, {%4,%5,%6,%7}, {%8,%9}, {%0,%1,%2,%3};"
        : "+f"(d[0]), "+f"(d[1]), "+f"(d[2]), "+f"(d[3])
        : "r"(a0), "r"(a1), "r"(a2), "r"(a3), "r"(b0), "r"(b1));
}
__device__ __forceinline__ uint32_t pack_bf16(float lo, float hi) {
    __nv_bfloat162 h = __floats2bfloat162_rn(lo, hi);   // lo -> .x (low 16)
    return *(uint32_t*)&h;
}
// monotone float<->int map for atomicMin
__device__ __forceinline__ int   fmap(float f)  { int i = __float_as_int(f); return i < 0 ? (i ^ 0x7FFFFFFF) : i; }
__device__ __forceinline__ float funmap(int i)  { return __int_as_float(i < 0 ? (i ^ 0x7FFFFFFF) : i); }

// ---------------- scratch ----------------
__device__ float g_cbnorm[KK];
__device__ float g_znorm[NN];
__device__ float g_zt[(size_t)NN * DD];     // z transposed to [n][d]
__device__ int   g_idx[NN];
__device__ float g_partial[2048];
__device__ int   g_candk[(size_t)NN * CAP];
__device__ int   g_candk_ext[(size_t)NN * EXT];   // overflow spill
__device__ int   g_cnum[NN];

// ---------------- kernel 1a: codebook norms (exact sequential order, coalesced) ----
__global__ void cbnorm_kernel(const float* __restrict__ cb) {
    __shared__ float tile[128][65];
    const int t  = threadIdx.x;            // 128 threads, row per thread
    const int r0 = blockIdx.x * 128;
    float acc = 0.f;
    for (int p = 0; p < 4; p++) {
        __syncthreads();
        for (int i = t; i < 128 * 64; i += 128) {
            int row = i >> 6, dc = i & 63;
            tile[row][dc] = cb[(r0 + row) * DD + p * 64 + dc];
        }
        __syncthreads();
        #pragma unroll 8
        for (int d = 0; d < 64; d++) {
            float v = tile[t][d];
            acc = __fadd_rn(acc, __fmul_rn(v, v));
        }
    }
    g_cbnorm[r0 + t] = acc;
}

// ---------------- kernel 1b: z norms (proven exact order) ----------------
__global__ void znorm_kernel(const float* __restrict__ z) {
    int n = blockIdx.x * blockDim.x + threadIdx.x;
    if (n >= NN) return;
    int b  = n >> 10;
    int hw = n & 1023;
    const float* p = z + ((size_t)b << 18) + hw;
    float acc = 0.f;
    #pragma unroll 8
    for (int d = 0; d < DD; d++) {
        float v = p[(size_t)d << 10];
        acc = __fadd_rn(acc, __fmul_rn(v, v));
    }
    g_znorm[n] = acc;
}

// ---------------- kernel 1c: transpose z -> g_zt[n][d] ----------------
__global__ void transpose_kernel(const float* __restrict__ z) {
    __shared__ float tile[32][33];
    int b   = blockIdx.z;
    int hw0 = blockIdx.x * 32;
    int d0  = blockIdx.y * 32;
    int tx = threadIdx.x, ty = threadIdx.y;
    #pragma unroll
    for (int j = 0; j < 32; j += 8)
        tile[ty + j][tx] = z[((size_t)(b * DD + d0 + ty + j)) * HW + hw0 + tx];
    __syncthreads();
    #pragma unroll
    for (int j = 0; j < 32; j += 8)
        g_zt[((size_t)(b * HW + hw0 + ty + j)) * DD + d0 + tx] = tile[tx][ty + j];
}

// ---------------- kernel 2: bf16 MMA GEMM + fused min + windowed candidates ----
// 256 threads / 8 warps: 4 M-warps x 2 N-warps, warp tile 32x32.
// smem u32: As[16][128][8] | Bs[16][64][8] | cn[1024] | smin[128] | scnt[128]
//           | sck[128][16]  = 109 KB -> 2 CTA/SM
// Admission overflow (slots 16..63) spills straight to g_candk_ext.
__global__ void __launch_bounds__(256, 2)
mma_cand_kernel(const float* __restrict__ cb) {
    extern __shared__ uint32_t smu[];
    uint32_t* As   = smu;                         // 16384 u32
    uint32_t* Bs   = smu + 16 * 128 * 8;          // 8192 u32
    float*    cn   = (float*)(Bs + 16 * 64 * 8);  // 1024
    int*      smin = (int*)(cn + KK);             // 128
    int*      scnt = smin + 128;                  // 128
    int*      sck  = scnt + 128;                  // 128*16

    const int t    = threadIdx.x;
    const int lane = t & 31;
    const int wid  = t >> 5;
    const int wm   = wid & 3;            // 4 warps over M (32 rows)
    const int wn   = wid >> 2;           // 2 warps over N (32 cols)
    const int g    = lane >> 2;
    const int tg   = lane & 3;
    const int n0   = blockIdx.x * MT;

    for (int i = t; i < KK; i += 256) cn[i] = g_cbnorm[i];
    if (t < MT) { smin[t] = fmap(FLT_MAX); scnt[t] = 0; }

    // stage A: 128 rows x 256 k -> bf16, interleaved words
    for (int i4 = t; i4 < MT * DD / 4; i4 += 256) {
        int row = i4 >> 6, k4 = i4 & 63;
        float4 v = *(const float4*)(g_zt + (size_t)(n0 + row) * DD + k4 * 4);
        int ks = k4 >> 2;
        int q  = k4 & 3;
        int pos0 = (q < 2) ? q * 4 : (q - 2) * 4 + 1;   // q:0->0, 1->4, 2->1, 3->5
        uint32_t* dst = As + ((ks * MT + row) << 3);
        dst[pos0]     = pack_bf16(v.x, v.y);
        dst[pos0 + 2] = pack_bf16(v.z, v.w);
    }

    // per-lane zn for its 4 rows (mf 0/1 x row g/g+8)
    float znr[2][2];
    #pragma unroll
    for (int mf = 0; mf < 2; mf++) {
        znr[mf][0] = g_znorm[n0 + wm * 32 + mf * 16 + g];
        znr[mf][1] = g_znorm[n0 + wm * 32 + mf * 16 + g + 8];
    }

    for (int c = 0; c < NCH; c++) {
        const int c0 = c * NC;
        __syncthreads();   // prev admission done; Bs free (also A/init ready, iter 0)

        // stage B: 64 codes x 256 k -> bf16, interleaved words
        for (int i4 = t; i4 < NC * DD / 4; i4 += 256) {
            int row = i4 >> 6, k4 = i4 & 63;
            float4 v = *(const float4*)(cb + (size_t)(c0 + row) * DD + k4 * 4);
            int ks = k4 >> 2;
            int q  = k4 & 3;
            int pos0 = (q < 2) ? q * 4 : (q - 2) * 4 + 1;
            uint32_t* dst = Bs + ((ks * NC + row) << 3);
            dst[pos0]     = pack_bf16(v.x, v.y);
            dst[pos0 + 2] = pack_bf16(v.z, v.w);
        }
        __syncthreads();

        float acc[2][4][4];
        #pragma unroll
        for (int mf = 0; mf < 2; mf++)
            #pragma unroll
            for (int nf = 0; nf < 4; nf++)
                #pragma unroll
                for (int e = 0; e < 4; e++) acc[mf][nf][e] = 0.f;

        #pragma unroll 4
        for (int ks = 0; ks < KSP; ks++) {
            uint2 alo[2], ahi[2];
            #pragma unroll
            for (int mf = 0; mf < 2; mf++) {
                int r = wm * 32 + mf * 16 + g;
                alo[mf] = *(const uint2*)(As + ((ks * MT + r) << 3) + 2 * tg);
                ahi[mf] = *(const uint2*)(As + ((ks * MT + r + 8) << 3) + 2 * tg);
            }
            uint2 bf[4];
            #pragma unroll
            for (int nf = 0; nf < 4; nf++) {
                int cc = wn * 32 + nf * 8 + g;
                bf[nf] = *(const uint2*)(Bs + ((ks * NC + cc) << 3) + 2 * tg);
            }
            #pragma unroll
            for (int mf = 0; mf < 2; mf++)
                #pragma unroll
                for (int nf = 0; nf < 4; nf++)
                    mma_bf16(acc[mf][nf], alo[mf].x, ahi[mf].x, alo[mf].y, ahi[mf].y,
                             bf[nf].x, bf[nf].y);
        }

        // phase 1: per-row running min -> smem atomicMin
        float rmin[2][2];
        #pragma unroll
        for (int mf = 0; mf < 2; mf++) { rmin[mf][0] = FLT_MAX; rmin[mf][1] = FLT_MAX; }
        #pragma unroll
        for (int mf = 0; mf < 2; mf++)
            #pragma unroll
            for (int nf = 0; nf < 4; nf++) {
                int col0 = wn * 32 + nf * 8 + 2 * tg;
                float c0v = cn[c0 + col0], c1v = cn[c0 + col0 + 1];
                rmin[mf][0] = fminf(rmin[mf][0],
                    fminf((znr[mf][0] + c0v) - 2.f * acc[mf][nf][0],
                          (znr[mf][0] + c1v) - 2.f * acc[mf][nf][1]));
                rmin[mf][1] = fminf(rmin[mf][1],
                    fminf((znr[mf][1] + c0v) - 2.f * acc[mf][nf][2],
                          (znr[mf][1] + c1v) - 2.f * acc[mf][nf][3]));
            }
        #pragma unroll
        for (int mf = 0; mf < 2; mf++)
            #pragma unroll
            for (int rr = 0; rr < 2; rr++) {
                float m = rmin[mf][rr];
                m = fminf(m, __shfl_xor_sync(0xFFFFFFFFu, m, 1));
                m = fminf(m, __shfl_xor_sync(0xFFFFFFFFu, m, 2));
                rmin[mf][rr] = m;
            }
        if (tg == 0) {
            #pragma unroll
            for (int mf = 0; mf < 2; mf++) {
                atomicMin(&smin[wm * 32 + mf * 16 + g],     fmap(rmin[mf][0]));
                atomicMin(&smin[wm * 32 + mf * 16 + g + 8], fmap(rmin[mf][1]));
            }
        }
        __syncthreads();

        // phase 2: windowed admission vs updated running min (smem, spill to global)
        #pragma unroll
        for (int mf = 0; mf < 2; mf++) {
            int r0 = wm * 32 + mf * 16 + g;
            int r1 = r0 + 8;
            float th0 = funmap(smin[r0]) + WINDOW;
            float th1 = funmap(smin[r1]) + WINDOW;
            #pragma unroll
            for (int nf = 0; nf < 4; nf++) {
                int col0 = wn * 32 + nf * 8 + 2 * tg;
                float c0v = cn[c0 + col0], c1v = cn[c0 + col0 + 1];
                float d00 = (znr[mf][0] + c0v) - 2.f * acc[mf][nf][0];
                float d01 = (znr[mf][0] + c1v) - 2.f * acc[mf][nf][1];
                float d10 = (znr[mf][1] + c0v) - 2.f * acc[mf][nf][2];
                float d11 = (znr[mf][1] + c1v) - 2.f * acc[mf][nf][3];
                if (d00 <= th0) {
                    int p = atomicAdd(&scnt[r0], 1);
                    if (p < CAP) sck[r0 * CAP + p] = c0 + col0;
                    else if (p < CAP + EXT) g_candk_ext[(size_t)(n0 + r0) * EXT + (p - CAP)] = c0 + col0;
                }
                if (d01 <= th0) {
                    int p = atomicAdd(&scnt[r0], 1);
                    if (p < CAP) sck[r0 * CAP + p] = c0 + col0 + 1;
                    else if (p < CAP + EXT) g_candk_ext[(size_t)(n0 + r0) * EXT + (p - CAP)] = c0 + col0 + 1;
                }
                if (d10 <= th1) {
                    int p = atomicAdd(&scnt[r1], 1);
                    if (p < CAP) sck[r1 * CAP + p] = c0 + col0;
                    else if (p < CAP + EXT) g_candk_ext[(size_t)(n0 + r1) * EXT + (p - CAP)] = c0 + col0;
                }
                if (d11 <= th1) {
                    int p = atomicAdd(&scnt[r1], 1);
                    if (p < CAP) sck[r1 * CAP + p] = c0 + col0 + 1;
                    else if (p < CAP + EXT) g_candk_ext[(size_t)(n0 + r1) * EXT + (p - CAP)] = c0 + col0 + 1;
                }
            }
        }
    }
    __syncthreads();

    // flush per-row results
    if (t < MT) {
        int cnt = scnt[t];
        g_cnum[n0 + t] = (cnt > CAP + EXT) ? 255 : cnt;   // 255: never expected
        int m = (cnt > CAP) ? CAP : cnt;
        for (int q = 0; q < m; q++)
            g_candk[(size_t)(n0 + t) * CAP + q] = sck[t * CAP + q];
    }
}

// ---------------- kernel 2b: finalize — exact rescore of all candidates ----
// Warp per row; two-tier candidate list (smem-flushed + global spill).
// Bit-exact reference rounding + (dist, k) lowest-index tiebreak.
__global__ void finalize_kernel(const float* __restrict__ cb) {
    const int t = threadIdx.x, w = t >> 5, l = t & 31;
    const int n = blockIdx.x * 8 + w;

    const int cnum = g_cnum[n];
    const float zn = g_znorm[n];
    const float* zr = g_zt + (size_t)n * DD;
    float zv[8];
    #pragma unroll
    for (int j = 0; j < 8; j++) zv[j] = zr[l + 32 * j];

    float bd = FLT_MAX;
    int   bk = 0x7FFFFFFF;
    const int cmax = (cnum == 255) ? KK : cnum;   // full scan never expected
    for (int c = 0; c < cmax; c++) {
        int k;
        if (cnum == 255)  k = c;
        else if (c < CAP) k = g_candk[(size_t)n * CAP + c];
        else              k = g_candk_ext[(size_t)n * EXT + (c - CAP)];
        const float* er = cb + (size_t)k * DD;
        float s = 0.f;
        #pragma unroll
        for (int j = 0; j < 8; j++) s = fmaf(zv[j], er[l + 32 * j], s);
        #pragma unroll
        for (int off = 16; off; off >>= 1) s += __shfl_xor_sync(0xFFFFFFFFu, s, off);
        // reference rounding: RN( RN(zn + cn) - 2*dot )
        float dist = __fadd_rn(__fadd_rn(zn, g_cbnorm[k]), -2.0f * s);
        if (dist < bd || (dist == bd && k < bk)) { bd = dist; bk = k; }
    }
    if (l == 0) g_idx[n] = bk;
}

// ---------------- kernel 3: gather + zq_st + indices + loss partials ----------
#define GN 128
#define GD 32
__global__ void gather_kernel(const float* __restrict__ z,
                              const float* __restrict__ cb,
                              float* __restrict__ out,
                              int write_extra) {
    __shared__ int   sidx[GN];
    __shared__ float tile[GD][GN + 1];
    __shared__ float red[8];

    const int t   = threadIdx.x;
    const int n0  = blockIdx.x * GN;
    const int d0  = blockIdx.y * GD;
    const int b   = n0 >> 10;
    const int hw0 = n0 & 1023;

    if (t < GN) sidx[t] = g_idx[n0 + t];
    __syncthreads();

    const int w = t >> 5, l = t & 31;
    for (int nn = w; nn < GN; nn += 8)
        tile[l][nn] = cb[sidx[nn] * DD + d0 + l];
    __syncthreads();

    float lsum = 0.f;
    #pragma unroll
    for (int r = 0; r < (GD * GN) / 256; r++) {
        int i  = r * 256 + t;
        int dd = i >> 7;
        int n  = i & 127;
        int d  = d0 + dd;
        float q  = tile[dd][n];
        int   zi = ((b << 8) + d) * HW + hw0 + n;
        float zv = z[zi];
        float df = __fsub_rn(q, zv);
        out[zi] = __fadd_rn(zv, df);       // zq_st = zp + RN(zq - zp), bitwise
        lsum = fmaf(df, df, lsum);
    }

    #pragma unroll
    for (int off = 16; off; off >>= 1)
        lsum += __shfl_xor_sync(0xFFFFFFFFu, lsum, off);
    if (l == 0) red[w] = lsum;
    __syncthreads();
    if (t == 0) {
        float s = 0.f;
        #pragma unroll
        for (int i = 0; i < 8; i++) s += red[i];
        g_partial[blockIdx.y * gridDim.x + blockIdx.x] = s;
    }
    if (write_extra && blockIdx.y == 0 && t < GN)
        out[IDX_OFF + n0 + t] = (float)sidx[t];
}

// ---------------- kernel 4: finalize loss ----------------
__global__ void loss_kernel(float* __restrict__ out) {
    __shared__ float red[8];
    int t = threadIdx.x;
    float s = 0.f;
    #pragma unroll
    for (int i = 0; i < 8; i++)
        s += g_partial[t * 8 + i];
    #pragma unroll
    for (int off = 16; off; off >>= 1)
        s += __shfl_xor_sync(0xFFFFFFFFu, s, off);
    if ((t & 31) == 0) red[t >> 5] = s;
    __syncthreads();
    if (t == 0) {
        double tot = 0.0;
        #pragma unroll
        for (int i = 0; i < 8; i++) tot += (double)red[i];
        out[LOSS_OFF] = (float)(2.0 * tot / (double)ZQ_SIZE);
    }
}

// ---------------- launch ----------------
extern "C" void kernel_launch(void* const* d_in, const int* in_sizes, int n_in,
                              void* d_out, int out_size) {
    const float* z  = (const float*)d_in[0];
    const float* cb = (const float*)d_in[1];
    float* out = (float*)d_out;

    int write_extra = (out_size >= LOSS_OFF + 1) ? 1 : 0;

    cbnorm_kernel<<<KK / 128, 128>>>(cb);
    znorm_kernel<<<NN / 256, 256>>>(z);
    transpose_kernel<<<dim3(HW / 32, DD / 32, BB), dim3(32, 8)>>>(z);

    // smem: As 64K + Bs 32K + cn 4K + smin/scnt 1K + sck 8K = 109 KB
    size_t smem = (16 * 128 * 8 + 16 * 64 * 8 + KK + 128 + 128 + 128 * CAP) * 4;
    cudaFuncSetAttribute(mma_cand_kernel,
                         cudaFuncAttributeMaxDynamicSharedMemorySize, (int)smem);
    mma_cand_kernel<<<NN / MT, 256, smem>>>(cb);

    finalize_kernel<<<NN / 8, 256>>>(cb);

    gather_kernel<<<dim3(NN / GN, DD / GD), 256>>>(z, cb, out, write_extra);

    if (write_extra)
        loss_kernel<<<1, 256>>>(out);
}